// round 5
// baseline (speedup 1.0000x reference)
#include <cuda_runtime.h>

// Triplet margin loss, B=65536 rows, D=256 floats per row.
// HBM-bound streaming: 3 x 67MB reads. TWO rows per warp -> 12 front-batched
// LDG.128 per thread (2KB contiguous per tensor per warp), warp+block
// reduction, fence-free packed-atomic finalize (count+fixed-point sum in one
// 64-bit atomicAdd; no CCTL.IVALL).

static constexpr int B = 65536;
static constexpr int D4 = 64;             // 256 floats = 64 float4
static constexpr int ROWS_PER_WARP = 2;
static constexpr int WARPS_PER_BLOCK = 8;
static constexpr int THREADS = WARPS_PER_BLOCK * 32;
static constexpr int ROWS_PER_BLOCK = WARPS_PER_BLOCK * ROWS_PER_WARP;  // 16
static constexpr int BLOCKS = B / ROWS_PER_BLOCK;    // 4096

static constexpr int COUNT_SHIFT = 50;
// Max sum: ~1.3e11 * 256 = 3.4e13 < 2^50. Count max 4096 fits in [50:63].

// Zero at module load; last block resets it each launch (deterministic replays).
__device__ unsigned long long g_acc = 0ull;

__device__ __forceinline__ void acc_sq(float& acc, const float4& x, const float4& y) {
    float d;
    d = x.x - y.x; acc += d * d;
    d = x.y - y.y; acc += d * d;
    d = x.z - y.z; acc += d * d;
    d = x.w - y.w; acc += d * d;
}

__global__ void
triplet_loss_kernel(const float4* __restrict__ a,
                    const float4* __restrict__ p,
                    const float4* __restrict__ n,
                    float* __restrict__ out,
                    float inv_b) {
    const int warp_in_block = threadIdx.x >> 5;
    const int lane = threadIdx.x & 31;
    const long long warp_id = (long long)blockIdx.x * WARPS_PER_BLOCK + warp_in_block;
    // Warp streams 2 consecutive rows = 128 float4 contiguous per tensor.
    const long long base = warp_id * (ROWS_PER_WARP * D4);

    const float4* ar = a + base;
    const float4* pr = p + base;
    const float4* nr = n + base;

    // Front-batch all 12 float4 loads (MLP=12). Offsets lane, +32, +64, +96
    // cover 2048 contiguous bytes (rows 2w and 2w+1).
    float4 a0 = ar[lane];
    float4 a1 = ar[lane + 32];
    float4 a2 = ar[lane + 64];
    float4 a3 = ar[lane + 96];
    float4 p0 = pr[lane];
    float4 p1 = pr[lane + 32];
    float4 p2 = pr[lane + 64];
    float4 p3 = pr[lane + 96];
    float4 n0 = nr[lane];
    float4 n1 = nr[lane + 32];
    float4 n2 = nr[lane + 64];
    float4 n3 = nr[lane + 96];

    // Row 0 accumulators (elements 0..63 of float4 row) and row 1 (64..127).
    float dap2_0 = 0.f, dan2_0 = 0.f, dpn2_0 = 0.f;
    float dap2_1 = 0.f, dan2_1 = 0.f, dpn2_1 = 0.f;

    acc_sq(dap2_0, a0, p0); acc_sq(dap2_0, a1, p1);
    acc_sq(dan2_0, a0, n0); acc_sq(dan2_0, a1, n1);
    acc_sq(dpn2_0, p0, n0); acc_sq(dpn2_0, p1, n1);

    acc_sq(dap2_1, a2, p2); acc_sq(dap2_1, a3, p3);
    acc_sq(dan2_1, a2, n2); acc_sq(dan2_1, a3, n3);
    acc_sq(dpn2_1, p2, n2); acc_sq(dpn2_1, p3, n3);

    // Warp reduce the six partial sums.
    #pragma unroll
    for (int off = 16; off > 0; off >>= 1) {
        dap2_0 += __shfl_xor_sync(0xFFFFFFFFu, dap2_0, off);
        dan2_0 += __shfl_xor_sync(0xFFFFFFFFu, dan2_0, off);
        dpn2_0 += __shfl_xor_sync(0xFFFFFFFFu, dpn2_0, off);
        dap2_1 += __shfl_xor_sync(0xFFFFFFFFu, dap2_1, off);
        dan2_1 += __shfl_xor_sync(0xFFFFFFFFu, dan2_1, off);
        dpn2_1 += __shfl_xor_sync(0xFFFFFFFFu, dpn2_1, off);
    }

    __shared__ float warp_loss[WARPS_PER_BLOCK];
    if (lane == 0) {
        float dap0 = sqrtf(dap2_0), dan0 = sqrtf(dan2_0), dpn0 = sqrtf(dpn2_0);
        float dap1 = sqrtf(dap2_1), dan1 = sqrtf(dan2_1), dpn1 = sqrtf(dpn2_1);

        float ms0 = 1.0f + 2.0f / (expf(4.0f * dap0) + 1e-6f);
        float md0 = 1.0f + 2.0f / (expf(4.0f - 4.0f * dan0) + 1e-6f);
        float ms1 = 1.0f + 2.0f / (expf(4.0f * dap1) + 1e-6f);
        float md1 = 1.0f + 2.0f / (expf(4.0f - 4.0f * dan1) + 1e-6f);

        float loss0 = dap0 - 0.5f * (dan0 + dpn0) + ms0 + md0;
        float loss1 = dap1 - 0.5f * (dan1 + dpn1) + ms1 + md1;
        warp_loss[warp_in_block] = loss0 + loss1;
    }
    __syncthreads();

    if (threadIdx.x == 0) {
        float s = 0.f;
        #pragma unroll
        for (int i = 0; i < WARPS_PER_BLOCK; i++) s += warp_loss[i];

        // Fixed-point contribution: strictly positive (~3.2e7 per block).
        unsigned long long fixed = __float2ull_rn(s * 256.0f);
        unsigned long long contrib = (1ull << COUNT_SHIFT) + fixed;
        unsigned long long prev = atomicAdd(&g_acc, contrib);

        if ((prev >> COUNT_SHIFT) == (unsigned long long)(BLOCKS - 1)) {
            unsigned long long total_fixed =
                (prev + contrib) & ((1ull << COUNT_SHIFT) - 1ull);
            out[0] = (float)((double)total_fixed * (1.0 / 256.0)) * inv_b;
            // Reset for the next graph replay (no concurrent writers remain).
            atomicExch(&g_acc, 0ull);
        }
    }
}

extern "C" void kernel_launch(void* const* d_in, const int* in_sizes, int n_in,
                              void* d_out, int out_size) {
    const float4* a = (const float4*)d_in[0];
    const float4* p = (const float4*)d_in[1];
    const float4* n = (const float4*)d_in[2];
    float* out = (float*)d_out;

    triplet_loss_kernel<<<BLOCKS, THREADS>>>(a, p, n, out, 1.0f / (float)B);
}